// round 3
// baseline (speedup 1.0000x reference)
#include <cuda_runtime.h>
#include <cuda_bf16.h>
#include <math.h>

#define CROP 448
#define NR   56      // cells per side
#define NB   55      // blocks per side
#define B    48
#define IMG  512
#define TOP  32
#define RPC  2       // cell-rows per CTA in kernel 1
#define ROWS_STAGED (RPC * 8 + 2)   // 18

// Cell histogram scratch: [b][cell_r][cell_c][bin]
__device__ float g_hist[(size_t)B * NR * NR * 9];
// Per-cell sum of squares: [b][cell_r][cell_c]
__device__ float g_cellss[(size_t)B * NR * NR];

// ---------------------------------------------------------------------------
// Kernel 1: gray -> sqrt -> gradients -> per-cell 9-bin histograms (+cell ss)
// grid: (NR/RPC, B), block: 448 threads (one per crop column)
// ---------------------------------------------------------------------------
__global__ __launch_bounds__(CROP, 3) void hog_cells_kernel(
    const float* __restrict__ x, const float* __restrict__ coeffs,
    float* __restrict__ hist, float* __restrict__ cellss)
{
    __shared__ float sg[ROWS_STAGED][CROP];   // sqrt(gray) rows [r0-1, r0+16]

    const int crg = blockIdx.x;      // cell-row group 0..27
    const int b   = blockIdx.y;
    const int c   = threadIdx.x;     // crop column 0..447
    const int r0  = crg * (RPC * 8);

    const float c0 = coeffs[0], c1 = coeffs[1], c2 = coeffs[2];
    const float* base = x + (size_t)b * 3 * IMG * IMG;

    #pragma unroll 6
    for (int i = 0; i < ROWS_STAGED; i++) {
        int r = r0 - 1 + i;
        r = min(max(r, 0), CROP - 1);
        size_t off = (size_t)(r + TOP) * IMG + TOP + c;
        float v = c0 * base[off]
                + c1 * base[off + (size_t)IMG * IMG]
                + c2 * base[off + (size_t)2 * IMG * IMG];
        sg[i][c] = sqrtf(v);
    }
    __syncthreads();

    // sin/cos of k*20 degrees, k=1..8
    const float SN[8] = {0.342020143f, 0.642787610f, 0.866025404f, 0.984807753f,
                         0.984807753f, 0.866025404f, 0.642787610f, 0.342020143f};
    const float CS[8] = {0.939692621f, 0.766044443f, 0.500000000f, 0.173648178f,
                        -0.173648178f,-0.500000000f,-0.766044443f,-0.939692621f};

    for (int sub = 0; sub < RPC; sub++) {
        float h[9];
        #pragma unroll
        for (int k = 0; k < 9; k++) h[k] = 0.f;

        #pragma unroll
        for (int i = 0; i < 8; i++) {
            int li = sub * 8 + i;        // staged index of this row is li+1
            int r  = r0 + li;            // global crop row
            float gr = 0.f, gc = 0.f;
            if (r > 0 && r < CROP - 1) gr = sg[li + 2][c] - sg[li][c];
            if (c > 0 && c < CROP - 1) gc = sg[li + 1][c + 1] - sg[li + 1][c - 1];

            float mag = sqrtf(gr * gr + gc * gc) * (1.0f / 64.0f);

            // Fold direction into the upper half-plane.
            float u = gc, v = gr;
            if (gr < 0.f || (gr == 0.f && gc < 0.f)) { u = -u; v = -v; }

            int bin = 0;
            #pragma unroll
            for (int k = 0; k < 8; k++)
                bin += (CS[k] * v - SN[k] * u >= 0.f) ? 1 : 0;

            #pragma unroll
            for (int k = 0; k < 9; k++)
                h[k] += (k == bin) ? mag : 0.f;
        }

        // Reduce over the 8 columns of each cell (8 consecutive lanes).
        #pragma unroll
        for (int k = 0; k < 9; k++) {
            h[k] += __shfl_xor_sync(0xffffffffu, h[k], 1);
            h[k] += __shfl_xor_sync(0xffffffffu, h[k], 2);
            h[k] += __shfl_xor_sync(0xffffffffu, h[k], 4);
        }

        if ((c & 7) == 0) {
            int cell = c >> 3;   // 0..55
            int cr = crg * RPC + sub;
            size_t cidx = ((size_t)b * NR + cr) * NR + cell;
            float ss = 0.f;
            #pragma unroll
            for (int k = 0; k < 9; k++) {
                hist[cidx * 9 + k] = h[k];
                ss += h[k] * h[k];
            }
            cellss[cidx] = ss;
        }
    }
}

// ---------------------------------------------------------------------------
// Kernel 2: L2-Hys block normalization. One CTA per (b, I) block-row.
// 256 threads = 8 warps; warp w handles blocks J = w, w+8, ...
// ---------------------------------------------------------------------------
#define K2_THREADS 256

__global__ __launch_bounds__(K2_THREADS) void hog_blocks_kernel(
    const float* __restrict__ hist, const float* __restrict__ cellss,
    float* __restrict__ out)
{
    __shared__ float sh[2 * NR * 9];    // hist rows I, I+1 (1008)
    __shared__ float scs[2 * NR];       // cell ss rows I, I+1 (112)

    const int b = blockIdx.x / NB;
    const int I = blockIdx.x % NB;
    const int tid = threadIdx.x;

    const float* src = hist + ((size_t)b * NR + I) * NR * 9;
    #pragma unroll
    for (int e = tid; e < 2 * NR * 9; e += K2_THREADS) sh[e] = src[e];
    const float* cs = cellss + ((size_t)b * NR + I) * NR;
    if (tid < 2 * NR) scs[tid] = cs[tid];
    __syncthreads();

    const int w    = tid >> 5;
    const int lane = tid & 31;

    // J-invariant smem offsets for this lane's element(s):
    // element k of block J lives at sh[(g>>1)*504 + (J + (g&1))*9 + bin],
    // g = k/9, bin = k%9.
    const int g0 = lane / 9, b0 = lane - g0 * 9;
    const int off0 = (g0 >> 1) * (NR * 9) + (g0 & 1) * 9 + b0;
    const int k1 = 32 + lane;           // only lanes 0..3 use it
    const int g1 = k1 / 9, b1 = k1 - g1 * 9;
    const int off1 = (g1 >> 1) * (NR * 9) + (g1 & 1) * 9 + b1;

    float* obase = out + (size_t)blockIdx.x * (NB * 36);

    for (int J = w; J < NB; J += 8) {
        float inv1 = rsqrtf(scs[J] + scs[J + 1] + scs[NR + J] + scs[NR + J + 1]
                            + 1e-10f);

        float c0v = fminf(sh[off0 + J * 9] * inv1, 0.2f);
        float c1v = 0.f;
        if (lane < 4)
            c1v = fminf(sh[off1 + J * 9] * inv1, 0.2f);

        float ss = c0v * c0v + c1v * c1v;
        #pragma unroll
        for (int d = 16; d >= 1; d >>= 1)
            ss += __shfl_xor_sync(0xffffffffu, ss, d);
        float inv2 = rsqrtf(ss + 1e-10f);

        float* o = obase + J * 36;
        o[lane] = c0v * inv2;
        if (lane < 4) o[32 + lane] = c1v * inv2;
    }
}

// ---------------------------------------------------------------------------
extern "C" void kernel_launch(void* const* d_in, const int* in_sizes, int n_in,
                              void* d_out, int out_size)
{
    const float* x      = (const float*)d_in[0];
    const float* coeffs = (const float*)d_in[1];
    float* out          = (float*)d_out;

    float *hist, *cellss;
    cudaGetSymbolAddress((void**)&hist, g_hist);
    cudaGetSymbolAddress((void**)&cellss, g_cellss);

    dim3 g1(NR / RPC, B);
    hog_cells_kernel<<<g1, CROP>>>(x, coeffs, hist, cellss);

    hog_blocks_kernel<<<B * NB, K2_THREADS>>>(hist, cellss, out);
}

// round 4
// speedup vs baseline: 1.4637x; 1.4637x over previous
#include <cuda_runtime.h>
#include <cuda_bf16.h>
#include <math.h>

#define CROP 448
#define NR   56      // cells per side
#define NB   55      // blocks per side
#define B    48
#define IMG  512
#define TOP  32
#define QPR  112     // float4 quads per row (448/4)

// Cell histogram scratch: [b][cell_r][cell_c][bin]
__device__ float g_hist[(size_t)B * NR * NR * 9];
// Per-cell sum of squares: [b][cell_r][cell_c]
__device__ float g_cellss[(size_t)B * NR * NR];

// ---------------------------------------------------------------------------
// Kernel 1: gray -> sqrt -> gradients -> per-cell 9-bin histograms (+cell ss)
// grid: (NR, B), block: 448 threads (one per crop column)
// Staging is float4-vectorized: 1120 quads spread over 448 threads.
// ---------------------------------------------------------------------------
__global__ __launch_bounds__(CROP) void hog_cells_kernel(
    const float* __restrict__ x, const float* __restrict__ coeffs,
    float* __restrict__ hist, float* __restrict__ cellss)
{
    __shared__ float sg[10][CROP];   // sqrt(gray) rows [r0-1, r0+8]

    const int cr = blockIdx.x;       // cell row 0..55
    const int b  = blockIdx.y;
    const int c  = threadIdx.x;      // crop column 0..447
    const int r0 = cr * 8;

    const float c0 = coeffs[0], c1 = coeffs[1], c2 = coeffs[2];
    const float* base = x + (size_t)b * 3 * IMG * IMG;

    // Stage 10 rows of sqrt(gray): each (row, quad) = 3x LDG.128 + STS.128.
    #pragma unroll
    for (int e = c; e < 10 * QPR; e += CROP) {
        int i = e / QPR;
        int q = e - i * QPR;
        int r = min(max(r0 - 1 + i, 0), CROP - 1);
        const float4* p = (const float4*)(base + (size_t)(r + TOP) * IMG + TOP) + q;
        float4 a0 = p[0];
        float4 a1 = p[(IMG * IMG) / 4];
        float4 a2 = p[(2 * IMG * IMG) / 4];
        float4 g;
        g.x = sqrtf(fmaf(c0, a0.x, fmaf(c1, a1.x, c2 * a2.x)));
        g.y = sqrtf(fmaf(c0, a0.y, fmaf(c1, a1.y, c2 * a2.y)));
        g.z = sqrtf(fmaf(c0, a0.z, fmaf(c1, a1.z, c2 * a2.z)));
        g.w = sqrtf(fmaf(c0, a0.w, fmaf(c1, a1.w, c2 * a2.w)));
        *((float4*)&sg[i][q * 4]) = g;
    }
    __syncthreads();

    // sin/cos of k*20 degrees, k=1..8
    const float SN[8] = {0.342020143f, 0.642787610f, 0.866025404f, 0.984807753f,
                         0.984807753f, 0.866025404f, 0.642787610f, 0.342020143f};
    const float CS[8] = {0.939692621f, 0.766044443f, 0.500000000f, 0.173648178f,
                        -0.173648178f,-0.500000000f,-0.766044443f,-0.939692621f};

    float h[9];
    #pragma unroll
    for (int k = 0; k < 9; k++) h[k] = 0.f;

    #pragma unroll
    for (int i = 0; i < 8; i++) {
        int r = r0 + i;  // crop row
        float gr = 0.f, gc = 0.f;
        if (r > 0 && r < CROP - 1) gr = sg[i + 2][c] - sg[i][c];
        if (c > 0 && c < CROP - 1) gc = sg[i + 1][c + 1] - sg[i + 1][c - 1];

        float mag = sqrtf(gr * gr + gc * gc) * (1.0f / 64.0f);

        // Fold direction into the upper half-plane: angle(u,v) in [0,180).
        float u = gc, v = gr;
        if (gr < 0.f || (gr == 0.f && gc < 0.f)) { u = -u; v = -v; }

        // bin = number of boundary angles 20k (k=1..8) below angle(u,v)
        int bin = 0;
        #pragma unroll
        for (int k = 0; k < 8; k++)
            bin += (CS[k] * v - SN[k] * u >= 0.f) ? 1 : 0;

        #pragma unroll
        for (int k = 0; k < 9; k++)
            h[k] += (k == bin) ? mag : 0.f;
    }

    // Reduce over the 8 columns of each cell (8 consecutive lanes in a warp).
    #pragma unroll
    for (int k = 0; k < 9; k++) {
        h[k] += __shfl_xor_sync(0xffffffffu, h[k], 1);
        h[k] += __shfl_xor_sync(0xffffffffu, h[k], 2);
        h[k] += __shfl_xor_sync(0xffffffffu, h[k], 4);
    }

    if ((c & 7) == 0) {
        int cell = c >> 3;   // 0..55
        size_t cidx = ((size_t)b * NR + cr) * NR + cell;
        float ss = 0.f;
        #pragma unroll
        for (int k = 0; k < 9; k++) {
            hist[cidx * 9 + k] = h[k];
            ss += h[k] * h[k];
        }
        cellss[cidx] = ss;
    }
}

// ---------------------------------------------------------------------------
// Kernel 2: L2-Hys block normalization. One CTA per (b, I) block-row.
// 256 threads = 8 warps; warp w handles blocks J = w, w+8, ...
// ---------------------------------------------------------------------------
#define K2_THREADS 256

__global__ __launch_bounds__(K2_THREADS) void hog_blocks_kernel(
    const float* __restrict__ hist, const float* __restrict__ cellss,
    float* __restrict__ out)
{
    __shared__ float sh[2 * NR * 9];    // hist rows I, I+1 (1008)
    __shared__ float scs[2 * NR];       // cell ss rows I, I+1 (112)

    const int b = blockIdx.x / NB;
    const int I = blockIdx.x % NB;
    const int tid = threadIdx.x;

    const float* src = hist + ((size_t)b * NR + I) * NR * 9;
    #pragma unroll
    for (int e = tid; e < 2 * NR * 9; e += K2_THREADS) sh[e] = src[e];
    const float* cs = cellss + ((size_t)b * NR + I) * NR;
    if (tid < 2 * NR) scs[tid] = cs[tid];
    __syncthreads();

    const int w    = tid >> 5;
    const int lane = tid & 31;

    // J-invariant smem offsets: element k of block J lives at
    // sh[(g>>1)*504 + (J + (g&1))*9 + bin], g = k/9, bin = k%9.
    const int g0 = lane / 9, b0 = lane - g0 * 9;
    const int off0 = (g0 >> 1) * (NR * 9) + (g0 & 1) * 9 + b0;
    const int k1 = 32 + lane;           // only lanes 0..3 use it
    const int g1 = k1 / 9, b1 = k1 - g1 * 9;
    const int off1 = (g1 >> 1) * (NR * 9) + (g1 & 1) * 9 + b1;

    float* obase = out + (size_t)blockIdx.x * (NB * 36);

    for (int J = w; J < NB; J += 8) {
        float inv1 = rsqrtf(scs[J] + scs[J + 1] + scs[NR + J] + scs[NR + J + 1]
                            + 1e-10f);

        float c0v = fminf(sh[off0 + J * 9] * inv1, 0.2f);
        float c1v = 0.f;
        if (lane < 4)
            c1v = fminf(sh[off1 + J * 9] * inv1, 0.2f);

        float ss = c0v * c0v + c1v * c1v;
        #pragma unroll
        for (int d = 16; d >= 1; d >>= 1)
            ss += __shfl_xor_sync(0xffffffffu, ss, d);
        float inv2 = rsqrtf(ss + 1e-10f);

        float* o = obase + J * 36;
        o[lane] = c0v * inv2;
        if (lane < 4) o[32 + lane] = c1v * inv2;
    }
}

// ---------------------------------------------------------------------------
extern "C" void kernel_launch(void* const* d_in, const int* in_sizes, int n_in,
                              void* d_out, int out_size)
{
    const float* x      = (const float*)d_in[0];
    const float* coeffs = (const float*)d_in[1];
    float* out          = (float*)d_out;

    float *hist, *cellss;
    cudaGetSymbolAddress((void**)&hist, g_hist);
    cudaGetSymbolAddress((void**)&cellss, g_cellss);

    dim3 g1(NR, B);
    hog_cells_kernel<<<g1, CROP>>>(x, coeffs, hist, cellss);

    hog_blocks_kernel<<<B * NB, K2_THREADS>>>(hist, cellss, out);
}

// round 5
// speedup vs baseline: 1.7961x; 1.2271x over previous
#include <cuda_runtime.h>
#include <cuda_bf16.h>
#include <math.h>

#define CROP 448
#define NR   56      // cells per side
#define NB   55      // blocks per side
#define B    48
#define IMG  512
#define TOP  32
#define QPR  112     // float4 quads per row (448/4)
#define SGW  456     // padded smem row width: col c at index c+4

// Cell histogram scratch: [b][cell_r][cell_c][bin]
__device__ float g_hist[(size_t)B * NR * NR * 9];
// Per-cell sum of squares: [b][cell_r][cell_c]
__device__ float g_cellss[(size_t)B * NR * NR];

__device__ __forceinline__ float fsqrt_approx(float x) {
    float r;
    asm("sqrt.approx.f32 %0, %1;" : "=f"(r) : "f"(x));
    return r;
}

// ---------------------------------------------------------------------------
// Kernel 1: gray -> sqrt -> gradients -> per-cell prefix histograms (+cell ss)
// grid: (NR, B), block: 448 threads (one per crop column)
// ---------------------------------------------------------------------------
__global__ __launch_bounds__(CROP) void hog_cells_kernel(
    const float* __restrict__ x, const float* __restrict__ coeffs,
    float* __restrict__ hist, float* __restrict__ cellss)
{
    // Rows r0-1..r0+8 (reflected at image edges); col c at index c+4.
    // Index 3 / 452 hold reflected edge cols so gc vanishes at c=0/447.
    __shared__ float sg[10][SGW];

    const int cr = blockIdx.x;       // cell row 0..55
    const int b  = blockIdx.y;
    const int c  = threadIdx.x;      // crop column 0..447
    const int r0 = cr * 8;

    const float c0 = coeffs[0], c1 = coeffs[1], c2 = coeffs[2];
    const float* base = x + (size_t)b * 3 * IMG * IMG;

    // Stage 10 rows of sqrt(gray); reflection clamp makes boundary gr = 0.
    #pragma unroll
    for (int e = c; e < 10 * QPR; e += CROP) {
        int i = e / QPR;
        int q = e - i * QPR;
        int r = r0 - 1 + i;
        if (r < 0) r = -r;                       // -1 -> 1
        if (r > CROP - 1) r = 2 * (CROP - 1) - r; // 448 -> 446
        const float4* p = (const float4*)(base + (size_t)(r + TOP) * IMG + TOP) + q;
        float4 a0 = p[0];
        float4 a1 = p[(IMG * IMG) / 4];
        float4 a2 = p[(2 * IMG * IMG) / 4];
        float4 g;
        g.x = fsqrt_approx(fmaf(c0, a0.x, fmaf(c1, a1.x, c2 * a2.x)));
        g.y = fsqrt_approx(fmaf(c0, a0.y, fmaf(c1, a1.y, c2 * a2.y)));
        g.z = fsqrt_approx(fmaf(c0, a0.z, fmaf(c1, a1.z, c2 * a2.z)));
        g.w = fsqrt_approx(fmaf(c0, a0.w, fmaf(c1, a1.w, c2 * a2.w)));
        *((float4*)&sg[i][4 + q * 4]) = g;
    }
    __syncthreads();

    // Reflected edge columns: col -1 -> col 1, col 448 -> col 446.
    if (c < 20) {
        int i = c >> 1;
        if (c & 1) sg[i][452] = sg[i][450];   // col 448 := col 446
        else       sg[i][3]   = sg[i][5];     // col -1  := col 1
    }
    __syncthreads();

    // sin/cos of k*20 degrees, k=1..8
    const float SN[8] = {0.342020143f, 0.642787610f, 0.866025404f, 0.984807753f,
                         0.984807753f, 0.866025404f, 0.642787610f, 0.342020143f};
    const float CS[8] = {0.939692621f, 0.766044443f, 0.500000000f, 0.173648178f,
                        -0.173648178f,-0.500000000f,-0.766044443f,-0.939692621f};

    // Vertical register pipeline.
    float vreg[10];
    #pragma unroll
    for (int i = 0; i < 10; i++) vreg[i] = sg[i][c + 4];

    // Prefix histogram: H[k] = sum of mag over pixels with angle >= 20k (H[0]=all).
    float H[9];
    #pragma unroll
    for (int k = 0; k < 9; k++) H[k] = 0.f;

    #pragma unroll
    for (int i = 0; i < 8; i++) {
        float gr = vreg[i + 2] - vreg[i];
        float gc = sg[i + 1][c + 5] - sg[i + 1][c + 3];

        float mag = fsqrt_approx(fmaf(gr, gr, gc * gc));

        // Fold into upper half-plane: angle(u,v) in [0,180).
        bool neg = (gr < 0.f) || (gr == 0.f && gc < 0.f);
        float u  = neg ? -gc : gc;
        float vv = neg ? -gr : gr;

        H[0] += mag;
        #pragma unroll
        for (int k = 0; k < 8; k++) {
            float t = fmaf(CS[k], vv, -SN[k] * u);
            if (t >= 0.f) H[k + 1] += mag;
        }
    }

    // Reduce over the 8 columns of each cell (8 consecutive lanes in a warp).
    #pragma unroll
    for (int k = 0; k < 9; k++) {
        H[k] += __shfl_xor_sync(0xffffffffu, H[k], 1);
        H[k] += __shfl_xor_sync(0xffffffffu, H[k], 2);
        H[k] += __shfl_xor_sync(0xffffffffu, H[k], 4);
    }

    if ((c & 7) == 0) {
        int cell = c >> 3;   // 0..55
        size_t cidx = ((size_t)b * NR + cr) * NR + cell;
        float ss = 0.f;
        #pragma unroll
        for (int k = 0; k < 9; k++) {
            float hk = ((k < 8) ? (H[k] - H[k + 1]) : H[8]) * (1.0f / 64.0f);
            hist[cidx * 9 + k] = hk;
            ss += hk * hk;
        }
        cellss[cidx] = ss;
    }
}

// ---------------------------------------------------------------------------
// Kernel 2: L2-Hys block normalization. One CTA per (b, I) block-row.
// 256 threads = 8 warps; warp w handles blocks J = w, w+8, ...
// ---------------------------------------------------------------------------
#define K2_THREADS 256

__global__ __launch_bounds__(K2_THREADS) void hog_blocks_kernel(
    const float* __restrict__ hist, const float* __restrict__ cellss,
    float* __restrict__ out)
{
    __shared__ float sh[2 * NR * 9];    // hist rows I, I+1 (1008)
    __shared__ float scs[2 * NR];       // cell ss rows I, I+1 (112)

    const int b = blockIdx.x / NB;
    const int I = blockIdx.x % NB;
    const int tid = threadIdx.x;

    const float* src = hist + ((size_t)b * NR + I) * NR * 9;
    #pragma unroll
    for (int e = tid; e < 2 * NR * 9; e += K2_THREADS) sh[e] = src[e];
    const float* cs = cellss + ((size_t)b * NR + I) * NR;
    if (tid < 2 * NR) scs[tid] = cs[tid];
    __syncthreads();

    const int w    = tid >> 5;
    const int lane = tid & 31;

    // J-invariant smem offsets: element k of block J lives at
    // sh[(g>>1)*504 + (J + (g&1))*9 + bin], g = k/9, bin = k%9.
    const int g0 = lane / 9, b0 = lane - g0 * 9;
    const int off0 = (g0 >> 1) * (NR * 9) + (g0 & 1) * 9 + b0;
    const int k1 = 32 + lane;           // only lanes 0..3 use it
    const int g1 = k1 / 9, b1 = k1 - g1 * 9;
    const int off1 = (g1 >> 1) * (NR * 9) + (g1 & 1) * 9 + b1;

    float* obase = out + (size_t)blockIdx.x * (NB * 36);

    for (int J = w; J < NB; J += 8) {
        float inv1 = rsqrtf(scs[J] + scs[J + 1] + scs[NR + J] + scs[NR + J + 1]
                            + 1e-10f);

        float c0v = fminf(sh[off0 + J * 9] * inv1, 0.2f);
        float c1v = 0.f;
        if (lane < 4)
            c1v = fminf(sh[off1 + J * 9] * inv1, 0.2f);

        float ss = c0v * c0v + c1v * c1v;
        #pragma unroll
        for (int d = 16; d >= 1; d >>= 1)
            ss += __shfl_xor_sync(0xffffffffu, ss, d);
        float inv2 = rsqrtf(ss + 1e-10f);

        float* o = obase + J * 36;
        o[lane] = c0v * inv2;
        if (lane < 4) o[32 + lane] = c1v * inv2;
    }
}

// ---------------------------------------------------------------------------
extern "C" void kernel_launch(void* const* d_in, const int* in_sizes, int n_in,
                              void* d_out, int out_size)
{
    const float* x      = (const float*)d_in[0];
    const float* coeffs = (const float*)d_in[1];
    float* out          = (float*)d_out;

    float *hist, *cellss;
    cudaGetSymbolAddress((void**)&hist, g_hist);
    cudaGetSymbolAddress((void**)&cellss, g_cellss);

    dim3 g1(NR, B);
    hog_cells_kernel<<<g1, CROP>>>(x, coeffs, hist, cellss);

    hog_blocks_kernel<<<B * NB, K2_THREADS>>>(hist, cellss, out);
}

// round 7
// speedup vs baseline: 1.8399x; 1.0244x over previous
#include <cuda_runtime.h>
#include <cuda_bf16.h>
#include <math.h>

#define CROP 448
#define NR   56      // cells per side
#define NB   55      // blocks per side
#define B    48
#define IMG  512
#define TOP  32
#define QPR  112     // float4 quads per row (448/4)
#define SGW  456     // padded smem row width: col c at index c+4

// Cell histogram scratch: [b][cell_r][cell_c][bin]
__device__ float g_hist[(size_t)B * NR * NR * 9];
// Per-cell sum of squares: [b][cell_r][cell_c]
__device__ float g_cellss[(size_t)B * NR * NR];

__device__ __forceinline__ float fsqrt_approx(float x) {
    float r;
    asm("sqrt.approx.f32 %0, %1;" : "=f"(r) : "f"(x));
    return r;
}

// ---------------------------------------------------------------------------
// Kernel 1: gray -> sqrt -> gradients -> per-cell prefix histograms (+cell ss)
// grid: (NR, B), block: 448 threads (one per crop column)   [UNCHANGED]
// ---------------------------------------------------------------------------
__global__ __launch_bounds__(CROP) void hog_cells_kernel(
    const float* __restrict__ x, const float* __restrict__ coeffs,
    float* __restrict__ hist, float* __restrict__ cellss)
{
    __shared__ float sg[10][SGW];

    const int cr = blockIdx.x;       // cell row 0..55
    const int b  = blockIdx.y;
    const int c  = threadIdx.x;      // crop column 0..447
    const int r0 = cr * 8;

    const float c0 = coeffs[0], c1 = coeffs[1], c2 = coeffs[2];
    const float* base = x + (size_t)b * 3 * IMG * IMG;

    #pragma unroll
    for (int e = c; e < 10 * QPR; e += CROP) {
        int i = e / QPR;
        int q = e - i * QPR;
        int r = r0 - 1 + i;
        if (r < 0) r = -r;                        // -1 -> 1
        if (r > CROP - 1) r = 2 * (CROP - 1) - r; // 448 -> 446
        const float4* p = (const float4*)(base + (size_t)(r + TOP) * IMG + TOP) + q;
        float4 a0 = p[0];
        float4 a1 = p[(IMG * IMG) / 4];
        float4 a2 = p[(2 * IMG * IMG) / 4];
        float4 g;
        g.x = fsqrt_approx(fmaf(c0, a0.x, fmaf(c1, a1.x, c2 * a2.x)));
        g.y = fsqrt_approx(fmaf(c0, a0.y, fmaf(c1, a1.y, c2 * a2.y)));
        g.z = fsqrt_approx(fmaf(c0, a0.z, fmaf(c1, a1.z, c2 * a2.z)));
        g.w = fsqrt_approx(fmaf(c0, a0.w, fmaf(c1, a1.w, c2 * a2.w)));
        *((float4*)&sg[i][4 + q * 4]) = g;
    }
    __syncthreads();

    if (c < 20) {
        int i = c >> 1;
        if (c & 1) sg[i][452] = sg[i][450];   // col 448 := col 446
        else       sg[i][3]   = sg[i][5];     // col -1  := col 1
    }
    __syncthreads();

    const float SN[8] = {0.342020143f, 0.642787610f, 0.866025404f, 0.984807753f,
                         0.984807753f, 0.866025404f, 0.642787610f, 0.342020143f};
    const float CS[8] = {0.939692621f, 0.766044443f, 0.500000000f, 0.173648178f,
                        -0.173648178f,-0.500000000f,-0.766044443f,-0.939692621f};

    float vreg[10];
    #pragma unroll
    for (int i = 0; i < 10; i++) vreg[i] = sg[i][c + 4];

    float H[9];
    #pragma unroll
    for (int k = 0; k < 9; k++) H[k] = 0.f;

    #pragma unroll
    for (int i = 0; i < 8; i++) {
        float gr = vreg[i + 2] - vreg[i];
        float gc = sg[i + 1][c + 5] - sg[i + 1][c + 3];

        float mag = fsqrt_approx(fmaf(gr, gr, gc * gc));

        bool neg = (gr < 0.f) || (gr == 0.f && gc < 0.f);
        float u  = neg ? -gc : gc;
        float vv = neg ? -gr : gr;

        H[0] += mag;
        #pragma unroll
        for (int k = 0; k < 8; k++) {
            float t = fmaf(CS[k], vv, -SN[k] * u);
            if (t >= 0.f) H[k + 1] += mag;
        }
    }

    #pragma unroll
    for (int k = 0; k < 9; k++) {
        H[k] += __shfl_xor_sync(0xffffffffu, H[k], 1);
        H[k] += __shfl_xor_sync(0xffffffffu, H[k], 2);
        H[k] += __shfl_xor_sync(0xffffffffu, H[k], 4);
    }

    if ((c & 7) == 0) {
        int cell = c >> 3;
        size_t cidx = ((size_t)b * NR + cr) * NR + cell;
        float ss = 0.f;
        #pragma unroll
        for (int k = 0; k < 9; k++) {
            float hk = ((k < 8) ? (H[k] - H[k + 1]) : H[8]) * (1.0f / 64.0f);
            hist[cidx * 9 + k] = hk;
            ss += hk * hk;
        }
        cellss[cidx] = ss;
    }
}

// ---------------------------------------------------------------------------
// Kernel 2: L2-Hys block normalization. One CTA per (b, I) block-row.
// 256 threads = 8 warps. Lane l of warp w handles cell g=l&3 of block
// J = w + 8*(l>>2). ALL lanes run the full computation on a clamped Jc so
// the warp stays converged for the shuffles; only the store is guarded.
// ---------------------------------------------------------------------------
#define K2_THREADS 256
#define VSTRIDE 37          // padded per-block stride in vbuf (kills conflicts)

__global__ __launch_bounds__(K2_THREADS) void hog_blocks_kernel(
    const float* __restrict__ hist, const float* __restrict__ cellss,
    float* __restrict__ out)
{
    __shared__ float sh[2 * NR * 9];      // hist rows I, I+1 (1008)
    __shared__ float scs[2 * NR];         // cell ss rows I, I+1 (112)
    __shared__ float vbuf[NB * VSTRIDE];  // normalized blocks, padded stride

    const int b = blockIdx.x / NB;
    const int I = blockIdx.x % NB;
    const int tid = threadIdx.x;

    // Stage: hist rows as float4 (1008 floats = 252 float4), cell-ss scalars.
    {
        const float4* src4 = (const float4*)(hist + ((size_t)b * NR + I) * NR * 9);
        if (tid < 252) ((float4*)sh)[tid] = src4[tid];
        const float* cs = cellss + ((size_t)b * NR + I) * NR;
        if (tid < 2 * NR) scs[tid] = cs[tid];
    }
    __syncthreads();

    const int w    = tid >> 5;
    const int lane = tid & 31;
    const int g    = lane & 3;            // cell within block
    const int J    = w + 8 * (lane >> 2); // block column (may be >= NB)
    const int Jc   = (J < NB) ? J : (NB - 1);  // clamped for safe reads

    float inv1 = rsqrtf(scs[Jc] + scs[Jc + 1] + scs[NR + Jc] + scs[NR + Jc + 1]
                        + 1e-10f);

    // This lane's cell: row I + (g>>1), col Jc + (g&1).
    const float* cell = sh + (g >> 1) * (NR * 9) + (Jc + (g & 1)) * 9;
    float v[9];
    float ss = 0.f;
    #pragma unroll
    for (int k = 0; k < 9; k++) {
        float f = fminf(cell[k] * inv1, 0.2f);
        v[k] = f;
        ss = fmaf(f, f, ss);
    }
    // Sum over the 4 lanes of this block's group (xor 1,2 stay in-group).
    // All 32 lanes participate (clamped lanes compute garbage, discarded).
    ss += __shfl_xor_sync(0xffffffffu, ss, 1);
    ss += __shfl_xor_sync(0xffffffffu, ss, 2);
    float inv2 = rsqrtf(ss + 1e-10f);

    if (J < NB) {
        float* dst = vbuf + J * VSTRIDE + g * 9;
        #pragma unroll
        for (int k = 0; k < 9; k++) dst[k] = v[k] * inv2;
    }
    __syncthreads();

    // Coalesced copy vbuf -> out (strip the padding).
    float* obase = out + (size_t)blockIdx.x * (NB * 36);
    #pragma unroll
    for (int e = tid; e < NB * 36; e += K2_THREADS) {
        int Jx = e / 36;
        int r  = e - Jx * 36;
        obase[e] = vbuf[Jx * VSTRIDE + r];
    }
}

// ---------------------------------------------------------------------------
extern "C" void kernel_launch(void* const* d_in, const int* in_sizes, int n_in,
                              void* d_out, int out_size)
{
    const float* x      = (const float*)d_in[0];
    const float* coeffs = (const float*)d_in[1];
    float* out          = (float*)d_out;

    float *hist, *cellss;
    cudaGetSymbolAddress((void**)&hist, g_hist);
    cudaGetSymbolAddress((void**)&cellss, g_cellss);

    dim3 g1(NR, B);
    hog_cells_kernel<<<g1, CROP>>>(x, coeffs, hist, cellss);

    hog_blocks_kernel<<<B * NB, K2_THREADS>>>(hist, cellss, out);
}